// round 13
// baseline (speedup 1.0000x reference)
#include <cuda_runtime.h>
#include <cuda_fp16.h>
#include <math.h>
#include <stdint.h>

#define B_SZ 4
#define SEQ  2048
#define DIM  1024
#define NH   16
#define HD   64
#define D3   3072
#define M_TOT (B_SZ * SEQ)

// Scratch (device globals — no runtime allocation allowed)
__device__ __half g_x16 [(size_t)M_TOT * DIM];   // x, fp16
__device__ __half g_w1h [(size_t)DIM * D3];      // w_qkv^T [3072][1024], fp16
__device__ __half g_w2h [(size_t)DIM * DIM];     // w_out^T [1024][1024], fp16
__device__ __half g_qkv [(size_t)M_TOT * D3];    // qkv, fp16
__device__ __half g_vT  [(size_t)B_SZ * NH * HD * SEQ];  // V^T [b,h,d,key], fp16
__device__ __half g_att [(size_t)M_TOT * DIM];   // attention out, fp16

// ---------------------------------------------------------------------------
// Helpers
// ---------------------------------------------------------------------------
__device__ __forceinline__ void mma_f16(float c[4], const uint32_t a[4], const uint32_t b[2]) {
    asm volatile(
        "mma.sync.aligned.m16n8k16.row.col.f32.f16.f16.f32 "
        "{%0,%1,%2,%3}, {%4,%5,%6,%7}, {%8,%9}, {%0,%1,%2,%3};"
        : "+f"(c[0]), "+f"(c[1]), "+f"(c[2]), "+f"(c[3])
        : "r"(a[0]), "r"(a[1]), "r"(a[2]), "r"(a[3]), "r"(b[0]), "r"(b[1]));
}
__device__ __forceinline__ void ldmx4(uint32_t& r0, uint32_t& r1, uint32_t& r2,
                                      uint32_t& r3, const void* p) {
    uint32_t a = (uint32_t)__cvta_generic_to_shared(p);
    asm volatile("ldmatrix.sync.aligned.m8n8.x4.shared.b16 {%0,%1,%2,%3}, [%4];"
                 : "=r"(r0), "=r"(r1), "=r"(r2), "=r"(r3) : "r"(a));
}
__device__ __forceinline__ void cpasync16(void* smem, const void* gmem) {
    uint32_t sa = (uint32_t)__cvta_generic_to_shared(smem);
    asm volatile("cp.async.cg.shared.global [%0], [%1], 16;" :: "r"(sa), "l"(gmem));
}
#define CP_COMMIT()  asm volatile("cp.async.commit_group;" ::: "memory")
#define CP_WAITG1()  asm volatile("cp.async.wait_group 1;" ::: "memory")
#define U32(p) (*(const uint32_t*)(p))

// ---------------------------------------------------------------------------
// Pre-kernels
// ---------------------------------------------------------------------------
__global__ __launch_bounds__(256) void round_h(
    const float* __restrict__ in, __half* __restrict__ out, int n4)
{
    int i = blockIdx.x * blockDim.x + threadIdx.x;
    int stride = gridDim.x * blockDim.x;
    for (; i < n4; i += stride) {
        float4 v = ((const float4*)in)[i];
        __half2 a = __floats2half2_rn(v.x, v.y);
        __half2 b = __floats2half2_rn(v.z, v.w);
        uint2 o;
        o.x = *(uint32_t*)&a;
        o.y = *(uint32_t*)&b;
        *(uint2*)&out[(size_t)i * 4] = o;
    }
}

// in [K][N] fp32 -> out [N][K] fp16
__global__ __launch_bounds__(256) void transpose_round_h(
    const float* __restrict__ in, __half* __restrict__ out, int K, int N)
{
    __shared__ float t[32][33];
    const int k0 = blockIdx.y * 32, n0 = blockIdx.x * 32;
    const int tx = threadIdx.x, ty = threadIdx.y;
#pragma unroll
    for (int j = 0; j < 4; ++j)
        t[ty + j * 8][tx] = in[(size_t)(k0 + ty + j * 8) * N + n0 + tx];
    __syncthreads();
#pragma unroll
    for (int j = 0; j < 4; ++j) {
        int row = ty + j * 8;
        out[(size_t)(n0 + row) * K + k0 + tx] = __float2half_rn(t[tx][row]);
    }
}

// V (fp16, qkv cols [2048,3072)) -> vT [b,h,d,key]. Coalesced both sides.
__global__ __launch_bounds__(256) void v_to_vT(
    const __half* __restrict__ qkv, __half* __restrict__ vT)
{
    __shared__ __half t[64 * 66];
    const int key0 = blockIdx.x * 64;
    const int h  = blockIdx.y;
    const int b  = blockIdx.z;
    const int tid = threadIdx.x;
#pragma unroll
    for (int i = 0; i < 8; ++i) {
        int idx = tid + i * 256;
        int key = idx >> 5, w = idx & 31;
        __half2 v = *(const __half2*)&qkv[(size_t)(b * SEQ + key0 + key) * D3
                                          + 2 * DIM + h * HD + w * 2];
        *(__half2*)&t[key * 66 + w * 2] = v;
    }
    __syncthreads();
#pragma unroll
    for (int i = 0; i < 8; ++i) {
        int idx = tid + i * 256;
        int d = idx >> 5, kw = idx & 31;
        __half2 o = __halves2half2(t[(2 * kw) * 66 + d], t[(2 * kw + 1) * 66 + d]);
        *(__half2*)&vT[(((size_t)b * NH + h) * HD + d) * SEQ + key0 + 2 * kw] = o;
    }
}

// ---------------------------------------------------------------------------
// fp16 TC GEMM: C = A@W + bias.  A [M][K] fp16, Wt [N][K] fp16.
// BM=BN=128, BK=32, 256 thr, 8 warps (2x4), warp tile 64x32, m16n8k16.
// Fragments loaded via ldmatrix.x4 (conflict-free at pitch 40 halves).
// 3-stage cp.async pipeline (wait_group 1).
// OUT_HALF=1: C fp16 (intermediate); OUT_HALF=0: C fp32 (final).
// ---------------------------------------------------------------------------
#define HP 40
#define HSTG (128 * HP)            // halves per operand stage (5120)
#define GSMEM (6 * HSTG * 2)       // bytes: 3 stages x (A+B) = 61440

template<int OUT_HALF>
__global__ __launch_bounds__(256, 2) void gemm_h(
    const __half* __restrict__ A, const __half* __restrict__ Wt,
    const float* __restrict__ bias, void* __restrict__ Cout,
    int M, int N, int K)
{
    extern __shared__ __half hsm[];

    const int tid  = threadIdx.x;
    const int lane = tid & 31;
    const int warp = tid >> 5;
    const int warpM = warp >> 2;      // 0..1
    const int warpN = warp & 3;       // 0..3
    const int g  = lane >> 2;
    const int t4 = lane & 3;
    const int mBase = blockIdx.y * 128;
    const int nBase = blockIdx.x * 128;

    // ldmatrix per-lane offsets (in halves)
    // A/x4 over 16 rows x 16 k: matrices (r0-7,k0-7)(r8-15,k0-7)(r0-7,k8-15)(r8-15,k8-15)
    const int laneA = (lane & 15) * HP + (lane >> 4) * 8;
    // B/x4 over 16 n-rows x 16 k: matrices (n0-7,k0-7)(n0-7,k8-15)(n8-15,k0-7)(n8-15,k8-15)
    const int laneB = (lane & 7) * HP + ((lane >> 3) & 1) * 8 + ((lane >> 4) & 1) * 8 * HP;

    // cp.async coords: 512 chunks per operand tile, 2 per thread
    int row_[2], c8_[2];
#pragma unroll
    for (int f = 0; f < 2; ++f) {
        int idx = tid + f * 256;
        row_[f] = idx >> 2;
        c8_[f]  = (idx & 3) * 8;
    }

    float acc[4][4][4];
#pragma unroll
    for (int mi = 0; mi < 4; ++mi)
#pragma unroll
        for (int ni = 0; ni < 4; ++ni)
#pragma unroll
            for (int r = 0; r < 4; ++r) acc[mi][ni][r] = 0.0f;

    auto loadStage = [&](int s, int k0) {
        __half* As = hsm + s * 2 * HSTG;
        __half* Bs = As + HSTG;
#pragma unroll
        for (int f = 0; f < 2; ++f) {
            int so = row_[f] * HP + c8_[f];
            cpasync16(&As[so], &A [(size_t)(mBase + row_[f]) * K + k0 + c8_[f]]);
            cpasync16(&Bs[so], &Wt[(size_t)(nBase + row_[f]) * K + k0 + c8_[f]]);
        }
    };

    loadStage(0, 0);
    CP_COMMIT();
    loadStage(1, 32);
    CP_COMMIT();

    const int nIter = K / 32;
    for (int i = 0; i < nIter; ++i) {
        const int s = i % 3;
        CP_WAITG1();
        __syncthreads();

        if (i + 2 < nIter)
            loadStage((i + 2) % 3, (i + 2) * 32);
        CP_COMMIT();

        const __half* As = hsm + s * 2 * HSTG;
        const __half* Bs = As + HSTG;
#pragma unroll
        for (int ss = 0; ss < 2; ++ss) {
            const int ko = ss * 16;
            uint32_t bfr[4][2];
#pragma unroll
            for (int nb = 0; nb < 2; ++nb)
                ldmx4(bfr[2 * nb][0], bfr[2 * nb][1],
                      bfr[2 * nb + 1][0], bfr[2 * nb + 1][1],
                      &Bs[(warpN * 32 + nb * 16) * HP + ko + laneB]);
#pragma unroll
            for (int mi = 0; mi < 4; ++mi) {
                uint32_t a[4];
                ldmx4(a[0], a[1], a[2], a[3],
                      &As[(warpM * 64 + mi * 16) * HP + ko + laneA]);
#pragma unroll
                for (int ni = 0; ni < 4; ++ni)
                    mma_f16(acc[mi][ni], a, bfr[ni]);
            }
        }
    }

    // Epilogue
#pragma unroll
    for (int mi = 0; mi < 4; ++mi) {
        int row0 = mBase + warpM * 64 + mi * 16 + g;
#pragma unroll
        for (int ni = 0; ni < 4; ++ni) {
            int col = nBase + warpN * 32 + ni * 8 + 2 * t4;
            float2 bv = *(const float2*)&bias[col];
            float v00 = acc[mi][ni][0] + bv.x;
            float v01 = acc[mi][ni][1] + bv.y;
            float v10 = acc[mi][ni][2] + bv.x;
            float v11 = acc[mi][ni][3] + bv.y;
            if (OUT_HALF) {
                __half* C = (__half*)Cout;
                __half2 o0 = __floats2half2_rn(v00, v01);
                __half2 o1 = __floats2half2_rn(v10, v11);
                *(__half2*)&C[(size_t)row0 * N + col]       = o0;
                *(__half2*)&C[(size_t)(row0 + 8) * N + col] = o1;
            } else {
                float* C = (float*)Cout;
                float2 o0 = {v00, v01};
                float2 o1 = {v10, v11};
                *(float2*)&C[(size_t)row0 * N + col]       = o0;
                *(float2*)&C[(size_t)(row0 + 8) * N + col] = o1;
            }
        }
    }
}

// ---------------------------------------------------------------------------
// Causal flash attention, fp16 MMA, fp32 softmax/accum.
// All fragments (Q hoist, K, P, V) via ldmatrix.x4 (pitch 72 halves = 144B
// -> row offsets mod 128B = 16r, perfectly conflict-free).
// 3-stage K/V cp.async pipeline.
// ---------------------------------------------------------------------------
#define AQP 72
#define KSTG (64 * AQP)
#define OFF_K (128 * AQP)
#define OFF_V (OFF_K + 3 * KSTG)
#define ATT_SMEM ((OFF_V + 3 * KSTG) * 2)      // bytes (73728)
#define ASCALE 0.1803368801111244f             // 0.125 * log2(e)

__global__ __launch_bounds__(256, 2) void attn_fwd_h(
    const __half* __restrict__ qkv, const __half* __restrict__ vT,
    __half* __restrict__ att)
{
    extern __shared__ __half hsm[];
    __half* QP = hsm;    // Q tile; rows [wrow,wrow+16) later reused for P

    const int qt = gridDim.x - 1 - blockIdx.x;   // longest-first
    const int h  = blockIdx.y;
    const int b  = blockIdx.z;
    const int qBase = qt * 128;
    const int tid  = threadIdx.x;
    const int lane = tid & 31;
    const int warp = tid >> 5;
    const int g  = lane >> 2;
    const int t4 = lane & 3;
    const int wrow = warp * 16;

    const int laneA = (lane & 15) * AQP + (lane >> 4) * 8;
    const int laneB = (lane & 7) * AQP + ((lane >> 3) & 1) * 8 + ((lane >> 4) & 1) * 8 * AQP;

    const __half* kvK = qkv + (size_t)(b * SEQ) * D3 + DIM + h * HD;
    const __half* vtb = vT + (((size_t)b * NH + h) * HD) * SEQ;
    const __half* qb  = qkv + (size_t)(b * SEQ + qBase) * D3 + h * HD;

    const int nkt = qBase / 64 + 2;

    auto loadKV = [&](int s, int kt) {
        __half* Ks = hsm + OFF_K + s * KSTG;
        __half* Vs = hsm + OFF_V + s * KSTG;
        const __half* srcK = kvK + (size_t)kt * 64 * D3;
        const __half* srcV = vtb + kt * 64;
#pragma unroll
        for (int it = 0; it < 2; ++it) {
            int i = tid + it * 256;
            int r = i >> 3, c8 = (i & 7) * 8;
            cpasync16(&Ks[r * AQP + c8], srcK + (size_t)r * D3 + c8);
            cpasync16(&Vs[r * AQP + c8], srcV + (size_t)r * SEQ + c8);
        }
    };

    // prologue: group0 = Q + KV tile 0; group1 = KV tile 1
    {
#pragma unroll
        for (int it = 0; it < 4; ++it) {
            int i = tid + it * 256;
            int r = i >> 3, c8 = (i & 7) * 8;
            cpasync16(&QP[r * AQP + c8], qb + (size_t)r * D3 + c8);
        }
        loadKV(0, 0);
        CP_COMMIT();
        loadKV(1, 1);
        CP_COMMIT();
    }

    // Wait for Q (group0) then hoist Q fragments via ldmatrix
    CP_WAITG1();
    __syncthreads();
    uint32_t qf[4][4];
#pragma unroll
    for (int s = 0; s < 4; ++s)
        ldmx4(qf[s][0], qf[s][1], qf[s][2], qf[s][3],
              &QP[wrow * AQP + s * 16 + laneA]);

    float m_i[2] = {-INFINITY, -INFINITY};
    float l_i[2] = {0.0f, 0.0f};
    float O[8][4];
#pragma unroll
    for (int ni = 0; ni < 8; ++ni)
#pragma unroll
        for (int r = 0; r < 4; ++r) O[ni][r] = 0.0f;

    for (int kt = 0; kt < nkt; ++kt) {
        const int stg = kt % 3;
        CP_WAITG1();
        __syncthreads();

        if (kt + 2 < nkt)
            loadKV((kt + 2) % 3, kt + 2);
        CP_COMMIT();

        const __half* Ks = hsm + OFF_K + stg * KSTG;
        const __half* Vs = hsm + OFF_V + stg * KSTG;
        const int ktBase = kt * 64;

        // S = Q K^T (raw), K frags via ldmatrix
        float sc[8][4];
#pragma unroll
        for (int ni = 0; ni < 8; ++ni)
#pragma unroll
            for (int r = 0; r < 4; ++r) sc[ni][r] = 0.0f;

#pragma unroll
        for (int s = 0; s < 4; ++s) {
            const int ko = s * 16;
            uint32_t bb[8][2];
#pragma unroll
            for (int nb = 0; nb < 4; ++nb)
                ldmx4(bb[2 * nb][0], bb[2 * nb][1],
                      bb[2 * nb + 1][0], bb[2 * nb + 1][1],
                      &Ks[(nb * 16) * AQP + ko + laneB]);
#pragma unroll
            for (int ni = 0; ni < 8; ++ni)
                mma_f16(sc[ni], qf[s], bb[ni]);
        }

        // scale (exact fp32) then causal mask
#pragma unroll
        for (int ni = 0; ni < 8; ++ni)
#pragma unroll
            for (int r = 0; r < 4; ++r) sc[ni][r] *= ASCALE;

        if (ktBase + 63 > qBase + wrow) {
            const int r0 = qBase + wrow + g;
            const int r1 = r0 + 8;
#pragma unroll
            for (int ni = 0; ni < 8; ++ni) {
                int c0 = ktBase + ni * 8 + 2 * t4;
                int c1 = c0 + 1;
                if (c0 > r0) sc[ni][0] = -1e30f;
                if (c1 > r0) sc[ni][1] = -1e30f;
                if (c0 > r1) sc[ni][2] = -1e30f;
                if (c1 > r1) sc[ni][3] = -1e30f;
            }
        }

        // Online softmax (base-2), quad-reduce
#pragma unroll
        for (int hrow = 0; hrow < 2; ++hrow) {
            const int i0 = hrow * 2, i1 = hrow * 2 + 1;
            float tm = -INFINITY;
#pragma unroll
            for (int ni = 0; ni < 8; ++ni)
                tm = fmaxf(tm, fmaxf(sc[ni][i0], sc[ni][i1]));
            tm = fmaxf(tm, __shfl_xor_sync(0xffffffffu, tm, 1, 4));
            tm = fmaxf(tm, __shfl_xor_sync(0xffffffffu, tm, 2, 4));
            float m_new = fmaxf(m_i[hrow], tm);
            float alpha = exp2f(m_i[hrow] - m_new);
            float rs = 0.0f;
#pragma unroll
            for (int ni = 0; ni < 8; ++ni) {
                sc[ni][i0] = exp2f(sc[ni][i0] - m_new);
                sc[ni][i1] = exp2f(sc[ni][i1] - m_new);
                rs += sc[ni][i0] + sc[ni][i1];
            }
            rs += __shfl_xor_sync(0xffffffffu, rs, 1, 4);
            rs += __shfl_xor_sync(0xffffffffu, rs, 2, 4);
            l_i[hrow] = l_i[hrow] * alpha + rs;
            m_i[hrow] = m_new;
#pragma unroll
            for (int ni = 0; ni < 8; ++ni) {
                O[ni][i0] *= alpha;
                O[ni][i1] *= alpha;
            }
        }

        // P -> QP smem as fp16 (half2 stores, warp-private rows)
#pragma unroll
        for (int ni = 0; ni < 8; ++ni) {
            __half2 p0 = __floats2half2_rn(sc[ni][0], sc[ni][1]);
            __half2 p1 = __floats2half2_rn(sc[ni][2], sc[ni][3]);
            *(__half2*)&QP[(wrow + g    ) * AQP + ni * 8 + 2 * t4] = p0;
            *(__half2*)&QP[(wrow + g + 8) * AQP + ni * 8 + 2 * t4] = p1;
        }
        __syncwarp();

        // O += P @ V  (P and V frags via ldmatrix)
#pragma unroll
        for (int s = 0; s < 4; ++s) {
            const int ko = s * 16;
            uint32_t a[4];
            ldmx4(a[0], a[1], a[2], a[3], &QP[wrow * AQP + ko + laneA]);
            uint32_t bb[8][2];
#pragma unroll
            for (int nb = 0; nb < 4; ++nb)
                ldmx4(bb[2 * nb][0], bb[2 * nb][1],
                      bb[2 * nb + 1][0], bb[2 * nb + 1][1],
                      &Vs[(nb * 16) * AQP + ko + laneB]);
#pragma unroll
            for (int ni = 0; ni < 8; ++ni)
                mma_f16(O[ni], a, bb[ni]);
        }
    }

    // Epilogue: normalize, fp16, plain layout
    __half* ob = att + (size_t)(b * SEQ + qBase + wrow) * DIM + h * HD;
    const float inv0 = 1.0f / l_i[0];
    const float inv1 = 1.0f / l_i[1];
#pragma unroll
    for (int ni = 0; ni < 8; ++ni) {
        int col = ni * 8 + 2 * t4;
        __half2 o0 = __floats2half2_rn(O[ni][0] * inv0, O[ni][1] * inv0);
        __half2 o1 = __floats2half2_rn(O[ni][2] * inv1, O[ni][3] * inv1);
        *(__half2*)(ob + (size_t)(g    ) * DIM + col) = o0;
        *(__half2*)(ob + (size_t)(g + 8) * DIM + col) = o1;
    }
}

// ---------------------------------------------------------------------------
extern "C" void kernel_launch(void* const* d_in, const int* in_sizes, int n_in,
                              void* d_out, int out_size)
{
    const float* x     = (const float*)d_in[0];
    const float* w_qkv = (const float*)d_in[1];
    const float* b_qkv = (const float*)d_in[2];
    const float* w_out = (const float*)d_in[3];
    const float* b_out = (const float*)d_in[4];
    float* out = (float*)d_out;

    __half *x16, *w1h, *w2h, *qkv16, *vT16, *att16;
    cudaGetSymbolAddress((void**)&x16,   g_x16);
    cudaGetSymbolAddress((void**)&w1h,   g_w1h);
    cudaGetSymbolAddress((void**)&w2h,   g_w2h);
    cudaGetSymbolAddress((void**)&qkv16, g_qkv);
    cudaGetSymbolAddress((void**)&vT16,  g_vT);
    cudaGetSymbolAddress((void**)&att16, g_att);

    // 0) Convert inputs to fp16 (x plain; weights transposed to [N][K])
    round_h<<<512, 256>>>(x, x16, (int)((size_t)M_TOT * DIM / 4));
    transpose_round_h<<<dim3(D3 / 32, DIM / 32), dim3(32, 8)>>>(w_qkv, w1h, DIM, D3);
    transpose_round_h<<<dim3(DIM / 32, DIM / 32), dim3(32, 8)>>>(w_out, w2h, DIM, DIM);

    cudaFuncSetAttribute(gemm_h<1>, cudaFuncAttributeMaxDynamicSharedMemorySize, GSMEM);
    cudaFuncSetAttribute(gemm_h<0>, cudaFuncAttributeMaxDynamicSharedMemorySize, GSMEM);

    // 1) QKV projection (fp16 out)
    gemm_h<1><<<dim3(D3 / 128, M_TOT / 128), 256, GSMEM>>>(
        x16, w1h, b_qkv, qkv16, M_TOT, D3, DIM);

    // 1b) V -> V^T [b,h,d,key]
    v_to_vT<<<dim3(SEQ / 64, NH, B_SZ), 256>>>(qkv16, vT16);

    // 2) Causal flash attention (fp16 MMA, ldmatrix fragments)
    cudaFuncSetAttribute(attn_fwd_h, cudaFuncAttributeMaxDynamicSharedMemorySize, ATT_SMEM);
    attn_fwd_h<<<dim3(SEQ / 128, NH, B_SZ), 256, ATT_SMEM>>>(qkv16, vT16, att16);

    // 3) Output projection (fp32 out)
    gemm_h<0><<<dim3(DIM / 128, M_TOT / 128), 256, GSMEM>>>(
        att16, w2h, b_out, out, M_TOT, DIM, DIM);
}

// round 14
// speedup vs baseline: 1.4450x; 1.4450x over previous
#include <cuda_runtime.h>
#include <cuda_fp16.h>
#include <math.h>
#include <stdint.h>

#define B_SZ 4
#define SEQ  2048
#define DIM  1024
#define NH   16
#define HD   64
#define D3   3072
#define M_TOT (B_SZ * SEQ)

// Scratch (device globals — no runtime allocation allowed)
__device__ __half g_x16 [(size_t)M_TOT * DIM];   // x, fp16
__device__ __half g_w1h [(size_t)DIM * D3];      // w_qkv^T [3072][1024], fp16
__device__ __half g_w2h [(size_t)DIM * DIM];     // w_out^T [1024][1024], fp16
__device__ __half g_qkv [(size_t)M_TOT * D3];    // qkv, fp16
__device__ __half g_vT  [(size_t)B_SZ * NH * HD * SEQ];  // V^T [b,h,d,key], fp16
__device__ __half g_att [(size_t)M_TOT * DIM];   // attention out, fp16

// ---------------------------------------------------------------------------
// Helpers
// ---------------------------------------------------------------------------
__device__ __forceinline__ void mma_f16(float c[4], const uint32_t a[4], const uint32_t b[2]) {
    asm volatile(
        "mma.sync.aligned.m16n8k16.row.col.f32.f16.f16.f32 "
        "{%0,%1,%2,%3}, {%4,%5,%6,%7}, {%8,%9}, {%0,%1,%2,%3};"
        : "+f"(c[0]), "+f"(c[1]), "+f"(c[2]), "+f"(c[3])
        : "r"(a[0]), "r"(a[1]), "r"(a[2]), "r"(a[3]), "r"(b[0]), "r"(b[1]));
}
__device__ __forceinline__ void cpasync16(void* smem, const void* gmem) {
    uint32_t sa = (uint32_t)__cvta_generic_to_shared(smem);
    asm volatile("cp.async.cg.shared.global [%0], [%1], 16;" :: "r"(sa), "l"(gmem));
}
#define CP_COMMIT()  asm volatile("cp.async.commit_group;" ::: "memory")
#define CP_WAIT0()   asm volatile("cp.async.wait_all;" ::: "memory")
#define CP_WAITG1()  asm volatile("cp.async.wait_group 1;" ::: "memory")
#define U32(p) (*(const uint32_t*)(p))

// ---------------------------------------------------------------------------
// Pre-kernels
// ---------------------------------------------------------------------------
__global__ __launch_bounds__(256) void round_h(
    const float* __restrict__ in, __half* __restrict__ out, int n4)
{
    int i = blockIdx.x * blockDim.x + threadIdx.x;
    int stride = gridDim.x * blockDim.x;
    for (; i < n4; i += stride) {
        float4 v = ((const float4*)in)[i];
        __half2 a = __floats2half2_rn(v.x, v.y);
        __half2 b = __floats2half2_rn(v.z, v.w);
        uint2 o;
        o.x = *(uint32_t*)&a;
        o.y = *(uint32_t*)&b;
        *(uint2*)&out[(size_t)i * 4] = o;
    }
}

// in [K][N] fp32 -> out [N][K] fp16
__global__ __launch_bounds__(256) void transpose_round_h(
    const float* __restrict__ in, __half* __restrict__ out, int K, int N)
{
    __shared__ float t[32][33];
    const int k0 = blockIdx.y * 32, n0 = blockIdx.x * 32;
    const int tx = threadIdx.x, ty = threadIdx.y;
#pragma unroll
    for (int j = 0; j < 4; ++j)
        t[ty + j * 8][tx] = in[(size_t)(k0 + ty + j * 8) * N + n0 + tx];
    __syncthreads();
#pragma unroll
    for (int j = 0; j < 4; ++j) {
        int row = ty + j * 8;
        out[(size_t)(n0 + row) * K + k0 + tx] = __float2half_rn(t[tx][row]);
    }
}

// V (fp16, qkv cols [2048,3072)) -> vT [b,h,d,key]. Coalesced both sides.
__global__ __launch_bounds__(256) void v_to_vT(
    const __half* __restrict__ qkv, __half* __restrict__ vT)
{
    __shared__ __half t[64 * 66];
    const int key0 = blockIdx.x * 64;
    const int h  = blockIdx.y;
    const int b  = blockIdx.z;
    const int tid = threadIdx.x;
#pragma unroll
    for (int i = 0; i < 8; ++i) {
        int idx = tid + i * 256;
        int key = idx >> 5, w = idx & 31;
        __half2 v = *(const __half2*)&qkv[(size_t)(b * SEQ + key0 + key) * D3
                                          + 2 * DIM + h * HD + w * 2];
        *(__half2*)&t[key * 66 + w * 2] = v;
    }
    __syncthreads();
#pragma unroll
    for (int i = 0; i < 8; ++i) {
        int idx = tid + i * 256;
        int d = idx >> 5, kw = idx & 31;
        __half2 o = __halves2half2(t[(2 * kw) * 66 + d], t[(2 * kw + 1) * 66 + d]);
        *(__half2*)&vT[(((size_t)b * NH + h) * HD + d) * SEQ + key0 + 2 * kw] = o;
    }
}

// ---------------------------------------------------------------------------
// fp16 TC GEMM: C = A@W + bias.  A [M][K] fp16, Wt [N][K] fp16.
// BM=BN=128, BK=64, 256 thr, 8 warps (2x4), warp tile 64x32, m16n8k16.
// Scalar-LDS fragment loads (R12-proven pattern), pitch 72 halves
// (36 words == 4 mod 32 -> bank 4g + c, conflict-free per phase).
// 2-stage cp.async pipeline; 16 barriers total (half of BK=32).
// OUT_HALF=1: C fp16 (intermediate); OUT_HALF=0: C fp32 (final).
// ---------------------------------------------------------------------------
#define HP 72
#define HSTG (128 * HP)            // halves per operand stage (9216)
#define GSMEM (4 * HSTG * 2)       // bytes: 2 stages x (A+B) = 73728

template<int OUT_HALF>
__global__ __launch_bounds__(256, 2) void gemm_h(
    const __half* __restrict__ A, const __half* __restrict__ Wt,
    const float* __restrict__ bias, void* __restrict__ Cout,
    int M, int N, int K)
{
    extern __shared__ __half hsm[];

    const int tid  = threadIdx.x;
    const int lane = tid & 31;
    const int warp = tid >> 5;
    const int warpM = warp >> 2;      // 0..1
    const int warpN = warp & 3;       // 0..3
    const int g  = lane >> 2;
    const int t4 = lane & 3;
    const int mBase = blockIdx.y * 128;
    const int nBase = blockIdx.x * 128;

    // cp.async coords: 1024 chunks per operand tile (128 rows x 8), 4 per thread
    int row_[4], c8_[4];
#pragma unroll
    for (int f = 0; f < 4; ++f) {
        int idx = tid + f * 256;
        row_[f] = idx >> 3;
        c8_[f]  = (idx & 7) * 8;     // half offset of 16B chunk in the 64-wide row
    }

    float acc[4][4][4];
#pragma unroll
    for (int mi = 0; mi < 4; ++mi)
#pragma unroll
        for (int ni = 0; ni < 4; ++ni)
#pragma unroll
            for (int r = 0; r < 4; ++r) acc[mi][ni][r] = 0.0f;

    auto loadStage = [&](int s, int k0) {
        __half* As = hsm + s * 2 * HSTG;
        __half* Bs = As + HSTG;
#pragma unroll
        for (int f = 0; f < 4; ++f) {
            int so = row_[f] * HP + c8_[f];
            cpasync16(&As[so], &A [(size_t)(mBase + row_[f]) * K + k0 + c8_[f]]);
            cpasync16(&Bs[so], &Wt[(size_t)(nBase + row_[f]) * K + k0 + c8_[f]]);
        }
    };

    loadStage(0, 0);
    CP_COMMIT();

    const int nIter = K / 64;        // 16 for K=1024
    int stage = 0;
    for (int i = 0; i < nIter; ++i) {
        CP_WAIT0();
        __syncthreads();

        if (i + 1 < nIter) {
            loadStage(stage ^ 1, (i + 1) * 64);
            CP_COMMIT();
        }

        const __half* As = hsm + stage * 2 * HSTG;
        const __half* Bs = As + HSTG;
#pragma unroll
        for (int ss = 0; ss < 4; ++ss) {
            const int ko = ss * 16 + 2 * t4;
            uint32_t bfr[4][2];
#pragma unroll
            for (int ni = 0; ni < 4; ++ni) {
                int n = warpN * 32 + ni * 8 + g;
                bfr[ni][0] = U32(&Bs[n * HP + ko]);
                bfr[ni][1] = U32(&Bs[n * HP + ko + 8]);
            }
#pragma unroll
            for (int mi = 0; mi < 4; ++mi) {
                int m = warpM * 64 + mi * 16;
                uint32_t a[4];
                a[0] = U32(&As[(m + g    ) * HP + ko]);
                a[1] = U32(&As[(m + g + 8) * HP + ko]);
                a[2] = U32(&As[(m + g    ) * HP + ko + 8]);
                a[3] = U32(&As[(m + g + 8) * HP + ko + 8]);
#pragma unroll
                for (int ni = 0; ni < 4; ++ni)
                    mma_f16(acc[mi][ni], a, bfr[ni]);
            }
        }
        stage ^= 1;
    }

    // Epilogue
#pragma unroll
    for (int mi = 0; mi < 4; ++mi) {
        int row0 = mBase + warpM * 64 + mi * 16 + g;
#pragma unroll
        for (int ni = 0; ni < 4; ++ni) {
            int col = nBase + warpN * 32 + ni * 8 + 2 * t4;
            float2 bv = *(const float2*)&bias[col];
            float v00 = acc[mi][ni][0] + bv.x;
            float v01 = acc[mi][ni][1] + bv.y;
            float v10 = acc[mi][ni][2] + bv.x;
            float v11 = acc[mi][ni][3] + bv.y;
            if (OUT_HALF) {
                __half* C = (__half*)Cout;
                __half2 o0 = __floats2half2_rn(v00, v01);
                __half2 o1 = __floats2half2_rn(v10, v11);
                *(__half2*)&C[(size_t)row0 * N + col]       = o0;
                *(__half2*)&C[(size_t)(row0 + 8) * N + col] = o1;
            } else {
                float* C = (float*)Cout;
                float2 o0 = {v00, v01};
                float2 o1 = {v10, v11};
                *(float2*)&C[(size_t)row0 * N + col]       = o0;
                *(float2*)&C[(size_t)(row0 + 8) * N + col] = o1;
            }
        }
    }
}

// ---------------------------------------------------------------------------
// Causal flash attention, fp16 MMA, fp32 softmax/accum (R12 version, proven).
// CTA: 256 thr (8 warps), Q tile 128 rows, K/V tiles 64 keys.
// THREE-stage K/V cp.async pipeline (wait_group 1). Scalar-LDS fragments.
// ---------------------------------------------------------------------------
#define AQP 72   // halves pitch (36 words -> bank 4g+t4, conflict-free)
#define KSTG (64 * AQP)                        // halves per K (or V) stage
#define OFF_K (128 * AQP)                      // after Q/P tile
#define OFF_V (OFF_K + 3 * KSTG)
#define ATT_SMEM ((OFF_V + 3 * KSTG) * 2)      // bytes (73728)
#define ASCALE 0.1803368801111244f             // 0.125 * log2(e)

__global__ __launch_bounds__(256, 2) void attn_fwd_h(
    const __half* __restrict__ qkv, const __half* __restrict__ vT,
    __half* __restrict__ att)
{
    extern __shared__ __half hsm[];
    __half* QP = hsm;    // Q tile; rows [wrow,wrow+16) later reused for P

    const int qt = gridDim.x - 1 - blockIdx.x;   // longest-first
    const int h  = blockIdx.y;
    const int b  = blockIdx.z;
    const int qBase = qt * 128;
    const int tid  = threadIdx.x;
    const int lane = tid & 31;
    const int warp = tid >> 5;
    const int g  = lane >> 2;
    const int t4 = lane & 3;
    const int wrow = warp * 16;

    const __half* kvK = qkv + (size_t)(b * SEQ) * D3 + DIM + h * HD;
    const __half* vtb = vT + (((size_t)b * NH + h) * HD) * SEQ;
    const __half* qb  = qkv + (size_t)(b * SEQ + qBase) * D3 + h * HD;

    const int nkt = qBase / 64 + 2;   // >= 2 always

    auto loadKV = [&](int s, int kt) {
        __half* Ks = hsm + OFF_K + s * KSTG;
        __half* Vs = hsm + OFF_V + s * KSTG;
        const __half* srcK = kvK + (size_t)kt * 64 * D3;
        const __half* srcV = vtb + kt * 64;
#pragma unroll
        for (int it = 0; it < 2; ++it) {
            int i = tid + it * 256;
            int r = i >> 3, c8 = (i & 7) * 8;     // r in [0,64)
            cpasync16(&Ks[r * AQP + c8], srcK + (size_t)r * D3 + c8);
            cpasync16(&Vs[r * AQP + c8], srcV + (size_t)r * SEQ + c8);
        }
    };

    // prologue: group0 = Q + KV tile 0; group1 = KV tile 1
    {
#pragma unroll
        for (int it = 0; it < 4; ++it) {
            int i = tid + it * 256;
            int r = i >> 3, c8 = (i & 7) * 8;     // r in [0,128) for Q
            cpasync16(&QP[r * AQP + c8], qb + (size_t)r * D3 + c8);
        }
        loadKV(0, 0);
        CP_COMMIT();
        loadKV(1, 1);
        CP_COMMIT();
    }

    // Wait for Q (group0) then hoist Q fragments
    CP_WAITG1();
    __syncthreads();
    uint32_t qf[4][4];
#pragma unroll
    for (int s = 0; s < 4; ++s) {
        const int ko = s * 16 + 2 * t4;
        qf[s][0] = U32(&QP[(wrow + g    ) * AQP + ko]);
        qf[s][1] = U32(&QP[(wrow + g + 8) * AQP + ko]);
        qf[s][2] = U32(&QP[(wrow + g    ) * AQP + ko + 8]);
        qf[s][3] = U32(&QP[(wrow + g + 8) * AQP + ko + 8]);
    }

    float m_i[2] = {-INFINITY, -INFINITY};
    float l_i[2] = {0.0f, 0.0f};
    float O[8][4];
#pragma unroll
    for (int ni = 0; ni < 8; ++ni)
#pragma unroll
        for (int r = 0; r < 4; ++r) O[ni][r] = 0.0f;

    for (int kt = 0; kt < nkt; ++kt) {
        const int stg = kt % 3;
        CP_WAITG1();          // KV tile kt resident; kt+1 may be in flight
        __syncthreads();

        if (kt + 2 < nkt)
            loadKV((kt + 2) % 3, kt + 2);
        CP_COMMIT();

        const __half* Ks = hsm + OFF_K + stg * KSTG;
        const __half* Vs = hsm + OFF_V + stg * KSTG;
        const int ktBase = kt * 64;

        // S = Q K^T (raw)
        float sc[8][4];
#pragma unroll
        for (int ni = 0; ni < 8; ++ni)
#pragma unroll
            for (int r = 0; r < 4; ++r) sc[ni][r] = 0.0f;

#pragma unroll
        for (int s = 0; s < 4; ++s) {
            const int ko = s * 16 + 2 * t4;
#pragma unroll
            for (int ni = 0; ni < 8; ++ni) {
                uint32_t bb[2];
                bb[0] = U32(&Ks[(ni * 8 + g) * AQP + ko]);
                bb[1] = U32(&Ks[(ni * 8 + g) * AQP + ko + 8]);
                mma_f16(sc[ni], qf[s], bb);
            }
        }

        // scale (exact fp32) then causal mask
#pragma unroll
        for (int ni = 0; ni < 8; ++ni)
#pragma unroll
            for (int r = 0; r < 4; ++r) sc[ni][r] *= ASCALE;

        if (ktBase + 63 > qBase + wrow) {
            const int r0 = qBase + wrow + g;
            const int r1 = r0 + 8;
#pragma unroll
            for (int ni = 0; ni < 8; ++ni) {
                int c0 = ktBase + ni * 8 + 2 * t4;
                int c1 = c0 + 1;
                if (c0 > r0) sc[ni][0] = -1e30f;
                if (c1 > r0) sc[ni][1] = -1e30f;
                if (c0 > r1) sc[ni][2] = -1e30f;
                if (c1 > r1) sc[ni][3] = -1e30f;
            }
        }

        // Online softmax (base-2), quad-reduce
#pragma unroll
        for (int hrow = 0; hrow < 2; ++hrow) {
            const int i0 = hrow * 2, i1 = hrow * 2 + 1;
            float tm = -INFINITY;
#pragma unroll
            for (int ni = 0; ni < 8; ++ni)
                tm = fmaxf(tm, fmaxf(sc[ni][i0], sc[ni][i1]));
            tm = fmaxf(tm, __shfl_xor_sync(0xffffffffu, tm, 1, 4));
            tm = fmaxf(tm, __shfl_xor_sync(0xffffffffu, tm, 2, 4));
            float m_new = fmaxf(m_i[hrow], tm);
            float alpha = exp2f(m_i[hrow] - m_new);
            float rs = 0.0f;
#pragma unroll
            for (int ni = 0; ni < 8; ++ni) {
                sc[ni][i0] = exp2f(sc[ni][i0] - m_new);
                sc[ni][i1] = exp2f(sc[ni][i1] - m_new);
                rs += sc[ni][i0] + sc[ni][i1];
            }
            rs += __shfl_xor_sync(0xffffffffu, rs, 1, 4);
            rs += __shfl_xor_sync(0xffffffffu, rs, 2, 4);
            l_i[hrow] = l_i[hrow] * alpha + rs;
            m_i[hrow] = m_new;
#pragma unroll
            for (int ni = 0; ni < 8; ++ni) {
                O[ni][i0] *= alpha;
                O[ni][i1] *= alpha;
            }
        }

        // P -> QP smem as fp16 (half2 stores, warp-private rows)
#pragma unroll
        for (int ni = 0; ni < 8; ++ni) {
            __half2 p0 = __floats2half2_rn(sc[ni][0], sc[ni][1]);
            __half2 p1 = __floats2half2_rn(sc[ni][2], sc[ni][3]);
            *(__half2*)&QP[(wrow + g    ) * AQP + ni * 8 + 2 * t4] = p0;
            *(__half2*)&QP[(wrow + g + 8) * AQP + ni * 8 + 2 * t4] = p1;
        }
        __syncwarp();

        // O += P @ V  (B from V^T [d][key] -> contiguous key pairs)
#pragma unroll
        for (int s = 0; s < 4; ++s) {
            const int ko = s * 16 + 2 * t4;
            uint32_t a[4];
            a[0] = U32(&QP[(wrow + g    ) * AQP + ko]);
            a[1] = U32(&QP[(wrow + g + 8) * AQP + ko]);
            a[2] = U32(&QP[(wrow + g    ) * AQP + ko + 8]);
            a[3] = U32(&QP[(wrow + g + 8) * AQP + ko + 8]);
#pragma unroll
            for (int ni = 0; ni < 8; ++ni) {
                uint32_t bb[2];
                bb[0] = U32(&Vs[(ni * 8 + g) * AQP + ko]);
                bb[1] = U32(&Vs[(ni * 8 + g) * AQP + ko + 8]);
                mma_f16(O[ni], a, bb);
            }
        }
    }

    // Epilogue: normalize, fp16, plain layout
    __half* ob = att + (size_t)(b * SEQ + qBase + wrow) * DIM + h * HD;
    const float inv0 = 1.0f / l_i[0];
    const float inv1 = 1.0f / l_i[1];
#pragma unroll
    for (int ni = 0; ni < 8; ++ni) {
        int col = ni * 8 + 2 * t4;
        __half2 o0 = __floats2half2_rn(O[ni][0] * inv0, O[ni][1] * inv0);
        __half2 o1 = __floats2half2_rn(O[ni][2] * inv1, O[ni][3] * inv1);
        *(__half2*)(ob + (size_t)(g    ) * DIM + col) = o0;
        *(__half2*)(ob + (size_t)(g + 8) * DIM + col) = o1;
    }
}

// ---------------------------------------------------------------------------
extern "C" void kernel_launch(void* const* d_in, const int* in_sizes, int n_in,
                              void* d_out, int out_size)
{
    const float* x     = (const float*)d_in[0];
    const float* w_qkv = (const float*)d_in[1];
    const float* b_qkv = (const float*)d_in[2];
    const float* w_out = (const float*)d_in[3];
    const float* b_out = (const float*)d_in[4];
    float* out = (float*)d_out;

    __half *x16, *w1h, *w2h, *qkv16, *vT16, *att16;
    cudaGetSymbolAddress((void**)&x16,   g_x16);
    cudaGetSymbolAddress((void**)&w1h,   g_w1h);
    cudaGetSymbolAddress((void**)&w2h,   g_w2h);
    cudaGetSymbolAddress((void**)&qkv16, g_qkv);
    cudaGetSymbolAddress((void**)&vT16,  g_vT);
    cudaGetSymbolAddress((void**)&att16, g_att);

    // 0) Convert inputs to fp16 (x plain; weights transposed to [N][K])
    round_h<<<512, 256>>>(x, x16, (int)((size_t)M_TOT * DIM / 4));
    transpose_round_h<<<dim3(D3 / 32, DIM / 32), dim3(32, 8)>>>(w_qkv, w1h, DIM, D3);
    transpose_round_h<<<dim3(DIM / 32, DIM / 32), dim3(32, 8)>>>(w_out, w2h, DIM, DIM);

    cudaFuncSetAttribute(gemm_h<1>, cudaFuncAttributeMaxDynamicSharedMemorySize, GSMEM);
    cudaFuncSetAttribute(gemm_h<0>, cudaFuncAttributeMaxDynamicSharedMemorySize, GSMEM);

    // 1) QKV projection (fp16 out)
    gemm_h<1><<<dim3(D3 / 128, M_TOT / 128), 256, GSMEM>>>(
        x16, w1h, b_qkv, qkv16, M_TOT, D3, DIM);

    // 1b) V -> V^T [b,h,d,key]
    v_to_vT<<<dim3(SEQ / 64, NH, B_SZ), 256>>>(qkv16, vT16);

    // 2) Causal flash attention (fp16 MMA, 3-stage pipeline)
    cudaFuncSetAttribute(attn_fwd_h, cudaFuncAttributeMaxDynamicSharedMemorySize, ATT_SMEM);
    attn_fwd_h<<<dim3(SEQ / 128, NH, B_SZ), 256, ATT_SMEM>>>(qkv16, vT16, att16);

    // 3) Output projection (fp32 out)
    gemm_h<0><<<dim3(DIM / 128, M_TOT / 128), 256, GSMEM>>>(
        att16, w2h, b_out, out, M_TOT, DIM, DIM);
}

// round 15
// speedup vs baseline: 1.4889x; 1.0304x over previous
#include <cuda_runtime.h>
#include <cuda_fp16.h>
#include <math.h>
#include <stdint.h>

#define B_SZ 4
#define SEQ  2048
#define DIM  1024
#define NH   16
#define HD   64
#define D3   3072
#define M_TOT (B_SZ * SEQ)

// Scratch (device globals — no runtime allocation allowed)
__device__ __half g_x16 [(size_t)M_TOT * DIM];   // x, fp16
__device__ __half g_w1h [(size_t)DIM * D3];      // w_qkv^T [3072][1024], fp16
__device__ __half g_w2h [(size_t)DIM * DIM];     // w_out^T [1024][1024], fp16
__device__ __half g_qkv [(size_t)M_TOT * D3];    // qkv, fp16 (V cols unused)
__device__ __half g_vT  [(size_t)B_SZ * NH * HD * SEQ];  // V^T [b,h,d,key], fp16
__device__ __half g_att [(size_t)M_TOT * DIM];   // attention out, fp16

// ---------------------------------------------------------------------------
// Helpers
// ---------------------------------------------------------------------------
__device__ __forceinline__ void mma_f16(float c[4], const uint32_t a[4], const uint32_t b[2]) {
    asm volatile(
        "mma.sync.aligned.m16n8k16.row.col.f32.f16.f16.f32 "
        "{%0,%1,%2,%3}, {%4,%5,%6,%7}, {%8,%9}, {%0,%1,%2,%3};"
        : "+f"(c[0]), "+f"(c[1]), "+f"(c[2]), "+f"(c[3])
        : "r"(a[0]), "r"(a[1]), "r"(a[2]), "r"(a[3]), "r"(b[0]), "r"(b[1]));
}
__device__ __forceinline__ void cpasync16(void* smem, const void* gmem) {
    uint32_t sa = (uint32_t)__cvta_generic_to_shared(smem);
    asm volatile("cp.async.cg.shared.global [%0], [%1], 16;" :: "r"(sa), "l"(gmem));
}
#define CP_COMMIT()  asm volatile("cp.async.commit_group;" ::: "memory")
#define CP_WAIT0()   asm volatile("cp.async.wait_all;" ::: "memory")
#define CP_WAITG1()  asm volatile("cp.async.wait_group 1;" ::: "memory")
#define U32(p) (*(const uint32_t*)(p))
#define ASCALE 0.1803368801111244f             // 0.125 * log2(e)

// ---------------------------------------------------------------------------
// Pre-kernels
// ---------------------------------------------------------------------------
__global__ __launch_bounds__(256) void round_h(
    const float* __restrict__ in, __half* __restrict__ out, int n4)
{
    int i = blockIdx.x * blockDim.x + threadIdx.x;
    int stride = gridDim.x * blockDim.x;
    for (; i < n4; i += stride) {
        float4 v = ((const float4*)in)[i];
        __half2 a = __floats2half2_rn(v.x, v.y);
        __half2 b = __floats2half2_rn(v.z, v.w);
        uint2 o;
        o.x = *(uint32_t*)&a;
        o.y = *(uint32_t*)&b;
        *(uint2*)&out[(size_t)i * 4] = o;
    }
}

// in [K][N] fp32 -> out [N][K] fp16
__global__ __launch_bounds__(256) void transpose_round_h(
    const float* __restrict__ in, __half* __restrict__ out, int K, int N)
{
    __shared__ float t[32][33];
    const int k0 = blockIdx.y * 32, n0 = blockIdx.x * 32;
    const int tx = threadIdx.x, ty = threadIdx.y;
#pragma unroll
    for (int j = 0; j < 4; ++j)
        t[ty + j * 8][tx] = in[(size_t)(k0 + ty + j * 8) * N + n0 + tx];
    __syncthreads();
#pragma unroll
    for (int j = 0; j < 4; ++j) {
        int row = ty + j * 8;
        out[(size_t)(n0 + row) * K + k0 + tx] = __float2half_rn(t[tx][row]);
    }
}

// ---------------------------------------------------------------------------
// fp16 TC GEMM: C = A@W + bias.  A [M][K] fp16, Wt [N][K] fp16.
// BM=BN=128, BK=64, 256 thr, 8 warps (2x4), warp tile 64x32, m16n8k16.
// Scalar-LDS fragments, pitch 72 halves. 2-stage cp.async pipeline.
// OUT_HALF=1 (QKV): Q/K regions -> plain fp16 to C; V region (nBase>=2048)
//   -> written TRANSPOSED to vTout [b,h,d,key] via smem staging.
// OUT_HALF=0: C fp32 plain.
// ---------------------------------------------------------------------------
#define HP 72
#define HSTG (128 * HP)            // halves per operand stage (9216)
#define GSMEM (4 * HSTG * 2)       // bytes: 2 stages x (A+B) = 73728

template<int OUT_HALF>
__global__ __launch_bounds__(256, 2) void gemm_h(
    const __half* __restrict__ A, const __half* __restrict__ Wt,
    const float* __restrict__ bias, void* __restrict__ Cout,
    __half* __restrict__ vTout, int M, int N, int K)
{
    extern __shared__ __half hsm[];

    const int tid  = threadIdx.x;
    const int lane = tid & 31;
    const int warp = tid >> 5;
    const int warpM = warp >> 2;      // 0..1
    const int warpN = warp & 3;       // 0..3
    const int g  = lane >> 2;
    const int t4 = lane & 3;
    const int mBase = blockIdx.y * 128;
    const int nBase = blockIdx.x * 128;

    int row_[4], c8_[4];
#pragma unroll
    for (int f = 0; f < 4; ++f) {
        int idx = tid + f * 256;
        row_[f] = idx >> 3;
        c8_[f]  = (idx & 7) * 8;
    }

    float acc[4][4][4];
#pragma unroll
    for (int mi = 0; mi < 4; ++mi)
#pragma unroll
        for (int ni = 0; ni < 4; ++ni)
#pragma unroll
            for (int r = 0; r < 4; ++r) acc[mi][ni][r] = 0.0f;

    auto loadStage = [&](int s, int k0) {
        __half* As = hsm + s * 2 * HSTG;
        __half* Bs = As + HSTG;
#pragma unroll
        for (int f = 0; f < 4; ++f) {
            int so = row_[f] * HP + c8_[f];
            cpasync16(&As[so], &A [(size_t)(mBase + row_[f]) * K + k0 + c8_[f]]);
            cpasync16(&Bs[so], &Wt[(size_t)(nBase + row_[f]) * K + k0 + c8_[f]]);
        }
    };

    loadStage(0, 0);
    CP_COMMIT();

    const int nIter = K / 64;
    int stage = 0;
    for (int i = 0; i < nIter; ++i) {
        CP_WAIT0();
        __syncthreads();

        if (i + 1 < nIter) {
            loadStage(stage ^ 1, (i + 1) * 64);
            CP_COMMIT();
        }

        const __half* As = hsm + stage * 2 * HSTG;
        const __half* Bs = As + HSTG;
#pragma unroll
        for (int ss = 0; ss < 4; ++ss) {
            const int ko = ss * 16 + 2 * t4;
            uint32_t bfr[4][2];
#pragma unroll
            for (int ni = 0; ni < 4; ++ni) {
                int n = warpN * 32 + ni * 8 + g;
                bfr[ni][0] = U32(&Bs[n * HP + ko]);
                bfr[ni][1] = U32(&Bs[n * HP + ko + 8]);
            }
#pragma unroll
            for (int mi = 0; mi < 4; ++mi) {
                int m = warpM * 64 + mi * 16;
                uint32_t a[4];
                a[0] = U32(&As[(m + g    ) * HP + ko]);
                a[1] = U32(&As[(m + g + 8) * HP + ko]);
                a[2] = U32(&As[(m + g    ) * HP + ko + 8]);
                a[3] = U32(&As[(m + g + 8) * HP + ko + 8]);
#pragma unroll
                for (int ni = 0; ni < 4; ++ni)
                    mma_f16(acc[mi][ni], a, bfr[ni]);
            }
        }
        stage ^= 1;
    }

    // --------------------------- Epilogue ---------------------------
    if (OUT_HALF && nBase >= 2 * DIM) {
        // V region: stage transposed [d_local][key_local] in smem, pitch 136.
        __syncthreads();                       // mainloop reads done everywhere
        __half* st = hsm;                      // 128*136*2 = 34816 B < GSMEM
#pragma unroll
        for (int mi = 0; mi < 4; ++mi) {
            int r0 = warpM * 64 + mi * 16 + g;           // key_local
#pragma unroll
            for (int ni = 0; ni < 4; ++ni) {
                int c0 = warpN * 32 + ni * 8 + 2 * t4;   // d_local
                float b0 = bias[nBase + c0];
                float b1 = bias[nBase + c0 + 1];
                st[(c0    ) * 136 + r0    ] = __float2half_rn(acc[mi][ni][0] + b0);
                st[(c0 + 1) * 136 + r0    ] = __float2half_rn(acc[mi][ni][1] + b1);
                st[(c0    ) * 136 + r0 + 8] = __float2half_rn(acc[mi][ni][2] + b0);
                st[(c0 + 1) * 136 + r0 + 8] = __float2half_rn(acc[mi][ni][3] + b1);
            }
        }
        __syncthreads();
        const int b    = mBase >> 11;            // SEQ = 2048
        const int key0 = mBase & (SEQ - 1);
        const int hb   = (nBase - 2 * DIM) >> 6; // first head of this tile
#pragma unroll
        for (int f = 0; f < 8; ++f) {
            int idx = tid + f * 256;
            int dl = idx >> 4;                   // 0..127
            int kc = (idx & 15) * 8;             // 0..120
            uint4 v = *(const uint4*)&st[dl * 136 + kc];
            int hh = hb + (dl >> 6), dd = dl & 63;
            *(uint4*)&vTout[(((size_t)b * NH + hh) * HD + dd) * SEQ + key0 + kc] = v;
        }
    } else {
#pragma unroll
        for (int mi = 0; mi < 4; ++mi) {
            int row0 = mBase + warpM * 64 + mi * 16 + g;
#pragma unroll
            for (int ni = 0; ni < 4; ++ni) {
                int col = nBase + warpN * 32 + ni * 8 + 2 * t4;
                float2 bv = *(const float2*)&bias[col];
                float v00 = acc[mi][ni][0] + bv.x;
                float v01 = acc[mi][ni][1] + bv.y;
                float v10 = acc[mi][ni][2] + bv.x;
                float v11 = acc[mi][ni][3] + bv.y;
                if (OUT_HALF) {
                    __half* C = (__half*)Cout;
                    __half2 o0 = __floats2half2_rn(v00, v01);
                    __half2 o1 = __floats2half2_rn(v10, v11);
                    *(__half2*)&C[(size_t)row0 * N + col]       = o0;
                    *(__half2*)&C[(size_t)(row0 + 8) * N + col] = o1;
                } else {
                    float* C = (float*)Cout;
                    float2 o0 = {v00, v01};
                    float2 o1 = {v10, v11};
                    *(float2*)&C[(size_t)row0 * N + col]       = o0;
                    *(float2*)&C[(size_t)(row0 + 8) * N + col] = o1;
                }
            }
        }
    }
}

// ---------------------------------------------------------------------------
// Causal flash attention, fp16 MMA, fp32 softmax/accum.
// Q pre-scaled by 0.125*log2(e) at smem load (fp32 mul, fp16 store) -> no
// per-tile scale loop. 3-stage K/V cp.async pipeline. Scalar-LDS fragments.
// ---------------------------------------------------------------------------
#define AQP 72
#define KSTG (64 * AQP)
#define OFF_K (128 * AQP)
#define OFF_V (OFF_K + 3 * KSTG)
#define ATT_SMEM ((OFF_V + 3 * KSTG) * 2)      // bytes (73728)

__global__ __launch_bounds__(256, 2) void attn_fwd_h(
    const __half* __restrict__ qkv, const __half* __restrict__ vT,
    __half* __restrict__ att)
{
    extern __shared__ __half hsm[];
    __half* QP = hsm;    // Q tile; rows [wrow,wrow+16) later reused for P

    const int qt = gridDim.x - 1 - blockIdx.x;   // longest-first
    const int h  = blockIdx.y;
    const int b  = blockIdx.z;
    const int qBase = qt * 128;
    const int tid  = threadIdx.x;
    const int lane = tid & 31;
    const int warp = tid >> 5;
    const int g  = lane >> 2;
    const int t4 = lane & 3;
    const int wrow = warp * 16;

    const __half* kvK = qkv + (size_t)(b * SEQ) * D3 + DIM + h * HD;
    const __half* vtb = vT + (((size_t)b * NH + h) * HD) * SEQ;
    const __half* qb  = qkv + (size_t)(b * SEQ + qBase) * D3 + h * HD;

    const int nkt = qBase / 64 + 2;

    auto loadKV = [&](int s, int kt) {
        __half* Ks = hsm + OFF_K + s * KSTG;
        __half* Vs = hsm + OFF_V + s * KSTG;
        const __half* srcK = kvK + (size_t)kt * 64 * D3;
        const __half* srcV = vtb + kt * 64;
#pragma unroll
        for (int it = 0; it < 2; ++it) {
            int i = tid + it * 256;
            int r = i >> 3, c8 = (i & 7) * 8;
            cpasync16(&Ks[r * AQP + c8], srcK + (size_t)r * D3 + c8);
            cpasync16(&Vs[r * AQP + c8], srcV + (size_t)r * SEQ + c8);
        }
    };

    // prologue: async KV tiles 0,1; meanwhile load+scale Q via registers
    loadKV(0, 0);
    CP_COMMIT();
    loadKV(1, 1);
    CP_COMMIT();

#pragma unroll
    for (int f = 0; f < 4; ++f) {
        int i = tid + f * 256;
        int r = i >> 3, c8 = (i & 7) * 8;
        uint4 v = *(const uint4*)(qb + (size_t)r * D3 + c8);
        __half2* hp = (__half2*)&v;
#pragma unroll
        for (int j = 0; j < 4; ++j) {
            float2 fv = __half22float2(hp[j]);
            hp[j] = __floats2half2_rn(fv.x * ASCALE, fv.y * ASCALE);
        }
        *(uint4*)&QP[r * AQP + c8] = v;
    }
    __syncthreads();

    // Hoist Q fragments; QP rows become warp-private P
    uint32_t qf[4][4];
#pragma unroll
    for (int s = 0; s < 4; ++s) {
        const int ko = s * 16 + 2 * t4;
        qf[s][0] = U32(&QP[(wrow + g    ) * AQP + ko]);
        qf[s][1] = U32(&QP[(wrow + g + 8) * AQP + ko]);
        qf[s][2] = U32(&QP[(wrow + g    ) * AQP + ko + 8]);
        qf[s][3] = U32(&QP[(wrow + g + 8) * AQP + ko + 8]);
    }

    float m_i[2] = {-INFINITY, -INFINITY};
    float l_i[2] = {0.0f, 0.0f};
    float O[8][4];
#pragma unroll
    for (int ni = 0; ni < 8; ++ni)
#pragma unroll
        for (int r = 0; r < 4; ++r) O[ni][r] = 0.0f;

    for (int kt = 0; kt < nkt; ++kt) {
        const int stg = kt % 3;
        CP_WAITG1();
        __syncthreads();

        if (kt + 2 < nkt)
            loadKV((kt + 2) % 3, kt + 2);
        CP_COMMIT();

        const __half* Ks = hsm + OFF_K + stg * KSTG;
        const __half* Vs = hsm + OFF_V + stg * KSTG;
        const int ktBase = kt * 64;

        // S = Qscaled K^T (already in log2 domain)
        float sc[8][4];
#pragma unroll
        for (int ni = 0; ni < 8; ++ni)
#pragma unroll
            for (int r = 0; r < 4; ++r) sc[ni][r] = 0.0f;

#pragma unroll
        for (int s = 0; s < 4; ++s) {
            const int ko = s * 16 + 2 * t4;
#pragma unroll
            for (int ni = 0; ni < 8; ++ni) {
                uint32_t bb[2];
                bb[0] = U32(&Ks[(ni * 8 + g) * AQP + ko]);
                bb[1] = U32(&Ks[(ni * 8 + g) * AQP + ko + 8]);
                mma_f16(sc[ni], qf[s], bb);
            }
        }

        // Causal mask
        if (ktBase + 63 > qBase + wrow) {
            const int r0 = qBase + wrow + g;
            const int r1 = r0 + 8;
#pragma unroll
            for (int ni = 0; ni < 8; ++ni) {
                int c0 = ktBase + ni * 8 + 2 * t4;
                int c1 = c0 + 1;
                if (c0 > r0) sc[ni][0] = -1e30f;
                if (c1 > r0) sc[ni][1] = -1e30f;
                if (c0 > r1) sc[ni][2] = -1e30f;
                if (c1 > r1) sc[ni][3] = -1e30f;
            }
        }

        // Online softmax (base-2), quad-reduce
#pragma unroll
        for (int hrow = 0; hrow < 2; ++hrow) {
            const int i0 = hrow * 2, i1 = hrow * 2 + 1;
            float tm = -INFINITY;
#pragma unroll
            for (int ni = 0; ni < 8; ++ni)
                tm = fmaxf(tm, fmaxf(sc[ni][i0], sc[ni][i1]));
            tm = fmaxf(tm, __shfl_xor_sync(0xffffffffu, tm, 1, 4));
            tm = fmaxf(tm, __shfl_xor_sync(0xffffffffu, tm, 2, 4));
            float m_new = fmaxf(m_i[hrow], tm);
            float alpha = exp2f(m_i[hrow] - m_new);
            float rs = 0.0f;
#pragma unroll
            for (int ni = 0; ni < 8; ++ni) {
                sc[ni][i0] = exp2f(sc[ni][i0] - m_new);
                sc[ni][i1] = exp2f(sc[ni][i1] - m_new);
                rs += sc[ni][i0] + sc[ni][i1];
            }
            rs += __shfl_xor_sync(0xffffffffu, rs, 1, 4);
            rs += __shfl_xor_sync(0xffffffffu, rs, 2, 4);
            l_i[hrow] = l_i[hrow] * alpha + rs;
            m_i[hrow] = m_new;
#pragma unroll
            for (int ni = 0; ni < 8; ++ni) {
                O[ni][i0] *= alpha;
                O[ni][i1] *= alpha;
            }
        }

        // P -> QP smem as fp16 (half2 stores, warp-private rows)
#pragma unroll
        for (int ni = 0; ni < 8; ++ni) {
            __half2 p0 = __floats2half2_rn(sc[ni][0], sc[ni][1]);
            __half2 p1 = __floats2half2_rn(sc[ni][2], sc[ni][3]);
            *(__half2*)&QP[(wrow + g    ) * AQP + ni * 8 + 2 * t4] = p0;
            *(__half2*)&QP[(wrow + g + 8) * AQP + ni * 8 + 2 * t4] = p1;
        }
        __syncwarp();

        // O += P @ V  (B from V^T [d][key])
#pragma unroll
        for (int s = 0; s < 4; ++s) {
            const int ko = s * 16 + 2 * t4;
            uint32_t a[4];
            a[0] = U32(&QP[(wrow + g    ) * AQP + ko]);
            a[1] = U32(&QP[(wrow + g + 8) * AQP + ko]);
            a[2] = U32(&QP[(wrow + g    ) * AQP + ko + 8]);
            a[3] = U32(&QP[(wrow + g + 8) * AQP + ko + 8]);
#pragma unroll
            for (int ni = 0; ni < 8; ++ni) {
                uint32_t bb[2];
                bb[0] = U32(&Vs[(ni * 8 + g) * AQP + ko]);
                bb[1] = U32(&Vs[(ni * 8 + g) * AQP + ko + 8]);
                mma_f16(O[ni], a, bb);
            }
        }
    }

    // Epilogue: normalize, fp16, plain layout
    __half* ob = att + (size_t)(b * SEQ + qBase + wrow) * DIM + h * HD;
    const float inv0 = 1.0f / l_i[0];
    const float inv1 = 1.0f / l_i[1];
#pragma unroll
    for (int ni = 0; ni < 8; ++ni) {
        int col = ni * 8 + 2 * t4;
        __half2 o0 = __floats2half2_rn(O[ni][0] * inv0, O[ni][1] * inv0);
        __half2 o1 = __floats2half2_rn(O[ni][2] * inv1, O[ni][3] * inv1);
        *(__half2*)(ob + (size_t)(g    ) * DIM + col) = o0;
        *(__half2*)(ob + (size_t)(g + 8) * DIM + col) = o1;
    }
}

// ---------------------------------------------------------------------------
extern "C" void kernel_launch(void* const* d_in, const int* in_sizes, int n_in,
                              void* d_out, int out_size)
{
    const float* x     = (const float*)d_in[0];
    const float* w_qkv = (const float*)d_in[1];
    const float* b_qkv = (const float*)d_in[2];
    const float* w_out = (const float*)d_in[3];
    const float* b_out = (const float*)d_in[4];
    float* out = (float*)d_out;

    __half *x16, *w1h, *w2h, *qkv16, *vT16, *att16;
    cudaGetSymbolAddress((void**)&x16,   g_x16);
    cudaGetSymbolAddress((void**)&w1h,   g_w1h);
    cudaGetSymbolAddress((void**)&w2h,   g_w2h);
    cudaGetSymbolAddress((void**)&qkv16, g_qkv);
    cudaGetSymbolAddress((void**)&vT16,  g_vT);
    cudaGetSymbolAddress((void**)&att16, g_att);

    // 0) Convert inputs to fp16 (x plain; weights transposed to [N][K])
    round_h<<<512, 256>>>(x, x16, (int)((size_t)M_TOT * DIM / 4));
    transpose_round_h<<<dim3(D3 / 32, DIM / 32), dim3(32, 8)>>>(w_qkv, w1h, DIM, D3);
    transpose_round_h<<<dim3(DIM / 32, DIM / 32), dim3(32, 8)>>>(w_out, w2h, DIM, DIM);

    cudaFuncSetAttribute(gemm_h<1>, cudaFuncAttributeMaxDynamicSharedMemorySize, GSMEM);
    cudaFuncSetAttribute(gemm_h<0>, cudaFuncAttributeMaxDynamicSharedMemorySize, GSMEM);

    // 1) QKV projection (Q/K fp16 plain; V written transposed to vT)
    gemm_h<1><<<dim3(D3 / 128, M_TOT / 128), 256, GSMEM>>>(
        x16, w1h, b_qkv, qkv16, vT16, M_TOT, D3, DIM);

    // 2) Causal flash attention (fp16 MMA, Q pre-scaled, 3-stage pipeline)
    cudaFuncSetAttribute(attn_fwd_h, cudaFuncAttributeMaxDynamicSharedMemorySize, ATT_SMEM);
    attn_fwd_h<<<dim3(SEQ / 128, NH, B_SZ), 256, ATT_SMEM>>>(qkv16, vT16, att16);

    // 3) Output projection (fp32 out)
    gemm_h<0><<<dim3(DIM / 128, M_TOT / 128), 256, GSMEM>>>(
        att16, w2h, b_out, out, nullptr, M_TOT, DIM, DIM);
}

// round 16
// speedup vs baseline: 1.4982x; 1.0063x over previous
#include <cuda_runtime.h>
#include <cuda_fp16.h>
#include <math.h>
#include <stdint.h>

#define B_SZ 4
#define SEQ  2048
#define DIM  1024
#define NH   16
#define HD   64
#define D3   3072
#define M_TOT (B_SZ * SEQ)

// Scratch (device globals — no runtime allocation allowed)
__device__ __half g_x16 [(size_t)M_TOT * DIM];   // x, fp16
__device__ __half g_w1h [(size_t)DIM * D3];      // w_qkv^T [3072][1024], fp16
__device__ __half g_w2h [(size_t)DIM * DIM];     // w_out^T [1024][1024], fp16
__device__ __half g_qkv [(size_t)M_TOT * D3];    // qkv, fp16 (V cols unused)
__device__ __half g_vT  [(size_t)B_SZ * NH * HD * SEQ];  // V^T [b,h,d,key], fp16
__device__ __half g_att [(size_t)M_TOT * DIM];   // attention out, fp16

// ---------------------------------------------------------------------------
// Helpers
// ---------------------------------------------------------------------------
__device__ __forceinline__ void mma_f16(float c[4], const uint32_t a[4], const uint32_t b[2]) {
    asm volatile(
        "mma.sync.aligned.m16n8k16.row.col.f32.f16.f16.f32 "
        "{%0,%1,%2,%3}, {%4,%5,%6,%7}, {%8,%9}, {%0,%1,%2,%3};"
        : "+f"(c[0]), "+f"(c[1]), "+f"(c[2]), "+f"(c[3])
        : "r"(a[0]), "r"(a[1]), "r"(a[2]), "r"(a[3]), "r"(b[0]), "r"(b[1]));
}
__device__ __forceinline__ void cpasync16(void* smem, const void* gmem) {
    uint32_t sa = (uint32_t)__cvta_generic_to_shared(smem);
    asm volatile("cp.async.cg.shared.global [%0], [%1], 16;" :: "r"(sa), "l"(gmem));
}
#define CP_COMMIT()  asm volatile("cp.async.commit_group;" ::: "memory")
#define CP_WAIT0()   asm volatile("cp.async.wait_all;" ::: "memory")
#define U32(p) (*(const uint32_t*)(p))
#define ASCALE 0.1803368801111244f             // 0.125 * log2(e)

// ---------------------------------------------------------------------------
// Fused pre-kernel: region-dispatched.
//  [0, 3072):       transpose+round w_qkv [1024][3072] -> w1h [3072][1024]
//  [3072, 4096):    transpose+round w_out [1024][1024] -> w2h [1024][1024]
//  [4096, 5120):    round x -> x16 (grid-stride, flat)
// block = (32, 8)
// ---------------------------------------------------------------------------
__global__ __launch_bounds__(256) void prep_h(
    const float* __restrict__ x,     __half* __restrict__ x16,
    const float* __restrict__ w_qkv, __half* __restrict__ w1h,
    const float* __restrict__ w_out, __half* __restrict__ w2h)
{
    __shared__ float t[32][33];
    const int tx = threadIdx.x, ty = threadIdx.y;
    const int bid = blockIdx.x;

    if (bid < 4096) {
        const float* in;
        __half* out;
        int K, N, tileIdx;
        if (bid < 3072) { in = w_qkv; out = w1h; K = DIM; N = D3;  tileIdx = bid; }
        else            { in = w_out; out = w2h; K = DIM; N = DIM; tileIdx = bid - 3072; }
        const int nTilesX = N / 32;
        const int n0 = (tileIdx % nTilesX) * 32;
        const int k0 = (tileIdx / nTilesX) * 32;
#pragma unroll
        for (int j = 0; j < 4; ++j)
            t[ty + j * 8][tx] = in[(size_t)(k0 + ty + j * 8) * N + n0 + tx];
        __syncthreads();
#pragma unroll
        for (int j = 0; j < 4; ++j) {
            int row = ty + j * 8;
            out[(size_t)(n0 + row) * K + k0 + tx] = __float2half_rn(t[tx][row]);
        }
    } else {
        const int n4 = (int)((size_t)M_TOT * DIM / 4);
        int i = (bid - 4096) * 256 + ty * 32 + tx;
        const int stride = 1024 * 256;
        for (; i < n4; i += stride) {
            float4 v = ((const float4*)x)[i];
            __half2 a = __floats2half2_rn(v.x, v.y);
            __half2 b = __floats2half2_rn(v.z, v.w);
            uint2 o;
            o.x = *(uint32_t*)&a;
            o.y = *(uint32_t*)&b;
            *(uint2*)&x16[(size_t)i * 4] = o;
        }
    }
}

// ---------------------------------------------------------------------------
// fp16 TC GEMM: C = A@W + bias.  A [M][K] fp16, Wt [N][K] fp16.
// BM=BN=128, BK=64, 256 thr, 8 warps (2x4), warp tile 64x32, m16n8k16.
// Scalar-LDS fragments, pitch 72 halves. 2-stage cp.async pipeline.
// OUT_HALF=1 (QKV): Q/K regions -> plain fp16 to C; V region (nBase>=2048)
//   -> written TRANSPOSED to vTout [b,h,d,key] via smem staging.
// OUT_HALF=0: C fp32 plain.
// ---------------------------------------------------------------------------
#define HP 72
#define HSTG (128 * HP)            // halves per operand stage (9216)
#define GSMEM (4 * HSTG * 2)       // bytes: 2 stages x (A+B) = 73728

template<int OUT_HALF>
__global__ __launch_bounds__(256, 2) void gemm_h(
    const __half* __restrict__ A, const __half* __restrict__ Wt,
    const float* __restrict__ bias, void* __restrict__ Cout,
    __half* __restrict__ vTout, int M, int N, int K)
{
    extern __shared__ __half hsm[];

    const int tid  = threadIdx.x;
    const int lane = tid & 31;
    const int warp = tid >> 5;
    const int warpM = warp >> 2;
    const int warpN = warp & 3;
    const int g  = lane >> 2;
    const int t4 = lane & 3;
    const int mBase = blockIdx.y * 128;
    const int nBase = blockIdx.x * 128;

    int row_[4], c8_[4];
#pragma unroll
    for (int f = 0; f < 4; ++f) {
        int idx = tid + f * 256;
        row_[f] = idx >> 3;
        c8_[f]  = (idx & 7) * 8;
    }

    float acc[4][4][4];
#pragma unroll
    for (int mi = 0; mi < 4; ++mi)
#pragma unroll
        for (int ni = 0; ni < 4; ++ni)
#pragma unroll
            for (int r = 0; r < 4; ++r) acc[mi][ni][r] = 0.0f;

    auto loadStage = [&](int s, int k0) {
        __half* As = hsm + s * 2 * HSTG;
        __half* Bs = As + HSTG;
#pragma unroll
        for (int f = 0; f < 4; ++f) {
            int so = row_[f] * HP + c8_[f];
            cpasync16(&As[so], &A [(size_t)(mBase + row_[f]) * K + k0 + c8_[f]]);
            cpasync16(&Bs[so], &Wt[(size_t)(nBase + row_[f]) * K + k0 + c8_[f]]);
        }
    };

    loadStage(0, 0);
    CP_COMMIT();

    const int nIter = K / 64;
    int stage = 0;
    for (int i = 0; i < nIter; ++i) {
        CP_WAIT0();
        __syncthreads();

        if (i + 1 < nIter) {
            loadStage(stage ^ 1, (i + 1) * 64);
            CP_COMMIT();
        }

        const __half* As = hsm + stage * 2 * HSTG;
        const __half* Bs = As + HSTG;
#pragma unroll
        for (int ss = 0; ss < 4; ++ss) {
            const int ko = ss * 16 + 2 * t4;
            uint32_t bfr[4][2];
#pragma unroll
            for (int ni = 0; ni < 4; ++ni) {
                int n = warpN * 32 + ni * 8 + g;
                bfr[ni][0] = U32(&Bs[n * HP + ko]);
                bfr[ni][1] = U32(&Bs[n * HP + ko + 8]);
            }
#pragma unroll
            for (int mi = 0; mi < 4; ++mi) {
                int m = warpM * 64 + mi * 16;
                uint32_t a[4];
                a[0] = U32(&As[(m + g    ) * HP + ko]);
                a[1] = U32(&As[(m + g + 8) * HP + ko]);
                a[2] = U32(&As[(m + g    ) * HP + ko + 8]);
                a[3] = U32(&As[(m + g + 8) * HP + ko + 8]);
#pragma unroll
                for (int ni = 0; ni < 4; ++ni)
                    mma_f16(acc[mi][ni], a, bfr[ni]);
            }
        }
        stage ^= 1;
    }

    // --------------------------- Epilogue ---------------------------
    if (OUT_HALF && nBase >= 2 * DIM) {
        __syncthreads();
        __half* st = hsm;
#pragma unroll
        for (int mi = 0; mi < 4; ++mi) {
            int r0 = warpM * 64 + mi * 16 + g;
#pragma unroll
            for (int ni = 0; ni < 4; ++ni) {
                int c0 = warpN * 32 + ni * 8 + 2 * t4;
                float b0 = bias[nBase + c0];
                float b1 = bias[nBase + c0 + 1];
                st[(c0    ) * 136 + r0    ] = __float2half_rn(acc[mi][ni][0] + b0);
                st[(c0 + 1) * 136 + r0    ] = __float2half_rn(acc[mi][ni][1] + b1);
                st[(c0    ) * 136 + r0 + 8] = __float2half_rn(acc[mi][ni][2] + b0);
                st[(c0 + 1) * 136 + r0 + 8] = __float2half_rn(acc[mi][ni][3] + b1);
            }
        }
        __syncthreads();
        const int b    = mBase >> 11;
        const int key0 = mBase & (SEQ - 1);
        const int hb   = (nBase - 2 * DIM) >> 6;
#pragma unroll
        for (int f = 0; f < 8; ++f) {
            int idx = tid + f * 256;
            int dl = idx >> 4;
            int kc = (idx & 15) * 8;
            uint4 v = *(const uint4*)&st[dl * 136 + kc];
            int hh = hb + (dl >> 6), dd = dl & 63;
            *(uint4*)&vTout[(((size_t)b * NH + hh) * HD + dd) * SEQ + key0 + kc] = v;
        }
    } else {
#pragma unroll
        for (int mi = 0; mi < 4; ++mi) {
            int row0 = mBase + warpM * 64 + mi * 16 + g;
#pragma unroll
            for (int ni = 0; ni < 4; ++ni) {
                int col = nBase + warpN * 32 + ni * 8 + 2 * t4;
                float2 bv = *(const float2*)&bias[col];
                float v00 = acc[mi][ni][0] + bv.x;
                float v01 = acc[mi][ni][1] + bv.y;
                float v10 = acc[mi][ni][2] + bv.x;
                float v11 = acc[mi][ni][3] + bv.y;
                if (OUT_HALF) {
                    __half* C = (__half*)Cout;
                    __half2 o0 = __floats2half2_rn(v00, v01);
                    __half2 o1 = __floats2half2_rn(v10, v11);
                    *(__half2*)&C[(size_t)row0 * N + col]       = o0;
                    *(__half2*)&C[(size_t)(row0 + 8) * N + col] = o1;
                } else {
                    float* C = (float*)Cout;
                    float2 o0 = {v00, v01};
                    float2 o1 = {v10, v11};
                    *(float2*)&C[(size_t)row0 * N + col]       = o0;
                    *(float2*)&C[(size_t)(row0 + 8) * N + col] = o1;
                }
            }
        }
    }
}

// ---------------------------------------------------------------------------
// Causal flash attention, fp16 MMA, fp32 softmax/accum.
// 128-key pipeline stages (2 buffers), TWO 64-key compute sub-tiles per
// stage: wait/sync/prefetch count halved vs 64-key stages.
// Q pre-scaled at smem load; P aliases Q smem; V as V^T [d][key].
// ---------------------------------------------------------------------------
#define AQP 72                         // Q/P/K row pitch (halves)
#define AVP 136                        // V^T row pitch for 128-key stage
#define KSK (128 * AQP)                // K stage halves (9216)
#define KSV (64 * AVP)                 // V stage halves (8704)
#define OFF_K (128 * AQP)              // after Q/P tile
#define OFF_V (OFF_K + 2 * KSK)
#define ATT_SMEM ((OFF_V + 2 * KSV) * 2)   // bytes (90112)

__global__ __launch_bounds__(256, 2) void attn_fwd_h(
    const __half* __restrict__ qkv, const __half* __restrict__ vT,
    __half* __restrict__ att)
{
    extern __shared__ __half hsm[];
    __half* QP = hsm;

    const int qt = gridDim.x - 1 - blockIdx.x;   // longest-first
    const int h  = blockIdx.y;
    const int b  = blockIdx.z;
    const int qBase = qt * 128;
    const int tid  = threadIdx.x;
    const int lane = tid & 31;
    const int warp = tid >> 5;
    const int g  = lane >> 2;
    const int t4 = lane & 3;
    const int wrow = warp * 16;

    const __half* kvK = qkv + (size_t)(b * SEQ) * D3 + DIM + h * HD;
    const __half* vtb = vT + (((size_t)b * NH + h) * HD) * SEQ;
    const __half* qb  = qkv + (size_t)(b * SEQ + qBase) * D3 + h * HD;

    const int nt2 = qBase / 128 + 1;   // 128-key stages

    auto loadKV2 = [&](int s, int t2) {
        __half* Ks = hsm + OFF_K + s * KSK;
        __half* Vs = hsm + OFF_V + s * KSV;
        const __half* srcK = kvK + (size_t)t2 * 128 * D3;
        const __half* srcV = vtb + t2 * 128;
#pragma unroll
        for (int it = 0; it < 4; ++it) {
            int i = tid + it * 256;
            int r = i >> 3, c8 = (i & 7) * 8;       // K: 128 rows x 8 chunks
            cpasync16(&Ks[r * AQP + c8], srcK + (size_t)r * D3 + c8);
        }
#pragma unroll
        for (int it = 0; it < 4; ++it) {
            int i = tid + it * 256;
            int d = i >> 4, kc = (i & 15) * 8;      // V: 64 rows x 16 chunks
            cpasync16(&Vs[d * AVP + kc], srcV + (size_t)d * SEQ + kc);
        }
    };

    // prologue: Q (scaled via registers) + KV stage 0 in one group
    loadKV2(0, 0);
#pragma unroll
    for (int f = 0; f < 4; ++f) {
        int i = tid + f * 256;
        int r = i >> 3, c8 = (i & 7) * 8;
        uint4 v = *(const uint4*)(qb + (size_t)r * D3 + c8);
        __half2* hp = (__half2*)&v;
#pragma unroll
        for (int j = 0; j < 4; ++j) {
            float2 fv = __half22float2(hp[j]);
            hp[j] = __floats2half2_rn(fv.x * ASCALE, fv.y * ASCALE);
        }
        *(uint4*)&QP[r * AQP + c8] = v;
    }
    CP_COMMIT();

    uint32_t qf[4][4];
    float m_i[2] = {-INFINITY, -INFINITY};
    float l_i[2] = {0.0f, 0.0f};
    float O[8][4];
#pragma unroll
    for (int ni = 0; ni < 8; ++ni)
#pragma unroll
        for (int r = 0; r < 4; ++r) O[ni][r] = 0.0f;

    for (int t2 = 0; t2 < nt2; ++t2) {
        const int stg = t2 & 1;
        CP_WAIT0();
        __syncthreads();

        if (t2 == 0) {
            // hoist Q fragments; QP rows become warp-private P afterwards
#pragma unroll
            for (int s = 0; s < 4; ++s) {
                const int ko = s * 16 + 2 * t4;
                qf[s][0] = U32(&QP[(wrow + g    ) * AQP + ko]);
                qf[s][1] = U32(&QP[(wrow + g + 8) * AQP + ko]);
                qf[s][2] = U32(&QP[(wrow + g    ) * AQP + ko + 8]);
                qf[s][3] = U32(&QP[(wrow + g + 8) * AQP + ko + 8]);
            }
        }

        if (t2 + 1 < nt2) {
            loadKV2(stg ^ 1, t2 + 1);
            CP_COMMIT();
        }

        const __half* Ks = hsm + OFF_K + stg * KSK;
        const __half* Vs = hsm + OFF_V + stg * KSV;

#pragma unroll
        for (int sub = 0; sub < 2; ++sub) {
            const int ktBase = t2 * 128 + sub * 64;
            const __half* Ksub = Ks + (size_t)sub * 64 * AQP;
            const int vofs = sub * 64;

            // S = Qscaled K^T
            float sc[8][4];
#pragma unroll
            for (int ni = 0; ni < 8; ++ni)
#pragma unroll
                for (int r = 0; r < 4; ++r) sc[ni][r] = 0.0f;

#pragma unroll
            for (int s = 0; s < 4; ++s) {
                const int ko = s * 16 + 2 * t4;
#pragma unroll
                for (int ni = 0; ni < 8; ++ni) {
                    uint32_t bb[2];
                    bb[0] = U32(&Ksub[(ni * 8 + g) * AQP + ko]);
                    bb[1] = U32(&Ksub[(ni * 8 + g) * AQP + ko + 8]);
                    mma_f16(sc[ni], qf[s], bb);
                }
            }

            // Causal mask
            if (ktBase + 63 > qBase + wrow) {
                const int r0 = qBase + wrow + g;
                const int r1 = r0 + 8;
#pragma unroll
                for (int ni = 0; ni < 8; ++ni) {
                    int c0 = ktBase + ni * 8 + 2 * t4;
                    int c1 = c0 + 1;
                    if (c0 > r0) sc[ni][0] = -1e30f;
                    if (c1 > r0) sc[ni][1] = -1e30f;
                    if (c0 > r1) sc[ni][2] = -1e30f;
                    if (c1 > r1) sc[ni][3] = -1e30f;
                }
            }

            // Online softmax (base-2), quad-reduce
#pragma unroll
            for (int hrow = 0; hrow < 2; ++hrow) {
                const int i0 = hrow * 2, i1 = hrow * 2 + 1;
                float tm = -INFINITY;
#pragma unroll
                for (int ni = 0; ni < 8; ++ni)
                    tm = fmaxf(tm, fmaxf(sc[ni][i0], sc[ni][i1]));
                tm = fmaxf(tm, __shfl_xor_sync(0xffffffffu, tm, 1, 4));
                tm = fmaxf(tm, __shfl_xor_sync(0xffffffffu, tm, 2, 4));
                float m_new = fmaxf(m_i[hrow], tm);
                float alpha = exp2f(m_i[hrow] - m_new);
                float rs = 0.0f;
#pragma unroll
                for (int ni = 0; ni < 8; ++ni) {
                    sc[ni][i0] = exp2f(sc[ni][i0] - m_new);
                    sc[ni][i1] = exp2f(sc[ni][i1] - m_new);
                    rs += sc[ni][i0] + sc[ni][i1];
                }
                rs += __shfl_xor_sync(0xffffffffu, rs, 1, 4);
                rs += __shfl_xor_sync(0xffffffffu, rs, 2, 4);
                l_i[hrow] = l_i[hrow] * alpha + rs;
                m_i[hrow] = m_new;
#pragma unroll
                for (int ni = 0; ni < 8; ++ni) {
                    O[ni][i0] *= alpha;
                    O[ni][i1] *= alpha;
                }
            }

            // P -> QP smem as fp16 (half2 stores, warp-private rows)
#pragma unroll
            for (int ni = 0; ni < 8; ++ni) {
                __half2 p0 = __floats2half2_rn(sc[ni][0], sc[ni][1]);
                __half2 p1 = __floats2half2_rn(sc[ni][2], sc[ni][3]);
                *(__half2*)&QP[(wrow + g    ) * AQP + ni * 8 + 2 * t4] = p0;
                *(__half2*)&QP[(wrow + g + 8) * AQP + ni * 8 + 2 * t4] = p1;
            }
            __syncwarp();

            // O += P @ V  (V^T rows = d, cols = keys; this sub's 64 keys)
#pragma unroll
            for (int s = 0; s < 4; ++s) {
                const int ko = s * 16 + 2 * t4;
                uint32_t a[4];
                a[0] = U32(&QP[(wrow + g    ) * AQP + ko]);
                a[1] = U32(&QP[(wrow + g + 8) * AQP + ko]);
                a[2] = U32(&QP[(wrow + g    ) * AQP + ko + 8]);
                a[3] = U32(&QP[(wrow + g + 8) * AQP + ko + 8]);
#pragma unroll
                for (int ni = 0; ni < 8; ++ni) {
                    uint32_t bb[2];
                    bb[0] = U32(&Vs[(ni * 8 + g) * AVP + vofs + ko]);
                    bb[1] = U32(&Vs[(ni * 8 + g) * AVP + vofs + ko + 8]);
                    mma_f16(O[ni], a, bb);
                }
            }
            __syncwarp();
        }
    }

    // Epilogue: normalize, fp16, plain layout
    __half* ob = att + (size_t)(b * SEQ + qBase + wrow) * DIM + h * HD;
    const float inv0 = 1.0f / l_i[0];
    const float inv1 = 1.0f / l_i[1];
#pragma unroll
    for (int ni = 0; ni < 8; ++ni) {
        int col = ni * 8 + 2 * t4;
        __half2 o0 = __floats2half2_rn(O[ni][0] * inv0, O[ni][1] * inv0);
        __half2 o1 = __floats2half2_rn(O[ni][2] * inv1, O[ni][3] * inv1);
        *(__half2*)(ob + (size_t)(g    ) * DIM + col) = o0;
        *(__half2*)(ob + (size_t)(g + 8) * DIM + col) = o1;
    }
}

// ---------------------------------------------------------------------------
extern "C" void kernel_launch(void* const* d_in, const int* in_sizes, int n_in,
                              void* d_out, int out_size)
{
    const float* x     = (const float*)d_in[0];
    const float* w_qkv = (const float*)d_in[1];
    const float* b_qkv = (const float*)d_in[2];
    const float* w_out = (const float*)d_in[3];
    const float* b_out = (const float*)d_in[4];
    float* out = (float*)d_out;

    __half *x16, *w1h, *w2h, *qkv16, *vT16, *att16;
    cudaGetSymbolAddress((void**)&x16,   g_x16);
    cudaGetSymbolAddress((void**)&w1h,   g_w1h);
    cudaGetSymbolAddress((void**)&w2h,   g_w2h);
    cudaGetSymbolAddress((void**)&qkv16, g_qkv);
    cudaGetSymbolAddress((void**)&vT16,  g_vT);
    cudaGetSymbolAddress((void**)&att16, g_att);

    // 0) Fused prep: x->fp16, weights transposed+rounded to [N][K]
    prep_h<<<5120, dim3(32, 8)>>>(x, x16, w_qkv, w1h, w_out, w2h);

    cudaFuncSetAttribute(gemm_h<1>, cudaFuncAttributeMaxDynamicSharedMemorySize, GSMEM);
    cudaFuncSetAttribute(gemm_h<0>, cudaFuncAttributeMaxDynamicSharedMemorySize, GSMEM);

    // 1) QKV projection (Q/K fp16 plain; V written transposed to vT)
    gemm_h<1><<<dim3(D3 / 128, M_TOT / 128), 256, GSMEM>>>(
        x16, w1h, b_qkv, qkv16, vT16, M_TOT, D3, DIM);

    // 2) Causal flash attention (fp16 MMA, 128-key stages, 2 sub-tiles)
    cudaFuncSetAttribute(attn_fwd_h, cudaFuncAttributeMaxDynamicSharedMemorySize, ATT_SMEM);
    attn_fwd_h<<<dim3(SEQ / 128, NH, B_SZ), 256, ATT_SMEM>>>(qkv16, vT16, att16);

    // 3) Output projection (fp32 out)
    gemm_h<0><<<dim3(DIM / 128, M_TOT / 128), 256, GSMEM>>>(
        att16, w2h, b_out, out, nullptr, M_TOT, DIM, DIM);
}